// round 16
// baseline (speedup 1.0000x reference)
#include <cuda_runtime.h>
#include <cstdint>

#define NUMEL        (8192 * 8192)
#define NGROUPS      (NUMEL / 4)              // 16,777,216 float4 groups
#define HALF_GROUPS  (NGROUPS / 2)            // codebook boundary
#define CB_ROWS      512

#define TPB          512
#define TILE_GROUPS  1024                     // 16KB out, 4KB codes, 64 scales
#define CODES_BYTES  (TILE_GROUPS * 4)        // 4096
#define SC_TILE      (TILE_GROUPS / 16)       // 64 scales per tile
#define SC_BYTES     (SC_TILE * 4)            // 256
#define NTILES       (NGROUPS / TILE_GROUPS)  // 16384
#define NIN          3                        // input triple-buffer
#define NOUT         2                        // output double-buffer
#define GRID         (148 * 4)                // 592 persistent CTAs, 4/SM

__device__ __forceinline__ uint32_t smem_u32(const void* p) {
    uint32_t a;
    asm("{ .reg .u64 t; cvta.to.shared.u64 t, %1; cvt.u32.u64 %0, t; }"
        : "=r"(a) : "l"(p));
    return a;
}

__device__ __forceinline__ void mbar_wait(uint32_t mb, int phase) {
    asm volatile(
        "{\n\t.reg .pred P;\n\t"
        "W%=:\n\t"
        "mbarrier.try_wait.parity.acquire.cta.shared::cta.b64 P, [%0], %1, 0x989680;\n\t"
        "@P bra D%=;\n\t"
        "bra W%=;\n\t"
        "D%=:\n\t}"
        :: "r"(mb), "r"(phase) : "memory");
}

__global__ __launch_bounds__(TPB, 4)
void dequant_kernel(const float4* __restrict__ codebooks,
                    const float*  __restrict__ scales,
                    const int*    __restrict__ codes,
                    float4*       __restrict__ out)
{
    __shared__ alignas(16) unsigned long long mbar[NIN];
    __shared__ float4 scb[CB_ROWS];                 // 8KB codebook
    __shared__ alignas(16) int   cbuf[NIN][TILE_GROUPS];  // 3 x 4KB codes
    __shared__ alignas(16) float sbuf[NIN][SC_TILE];      // 3 x 256B scales
    __shared__ float4 obuf[NOUT][TILE_GROUPS];      // 2 x 16KB out staging

    int t = threadIdx.x;
    scb[t] = codebooks[t];

    if (t == 0) {
        #pragma unroll
        for (int i = 0; i < NIN; i++) {
            uint32_t mb = smem_u32(&mbar[i]);
            asm volatile("mbarrier.init.shared.b64 [%0], 1;" :: "r"(mb) : "memory");
        }
        // Prologue: issue bulk loads for iterations 0 and 1.
        #pragma unroll
        for (int it0 = 0; it0 < 2; it0++) {
            unsigned int tl = blockIdx.x + (unsigned)it0 * GRID;   // < NTILES always
            uint32_t mb   = smem_u32(&mbar[it0]);
            uint32_t cdst = smem_u32(&cbuf[it0][0]);
            uint32_t sdst = smem_u32(&sbuf[it0][0]);
            asm volatile("mbarrier.arrive.expect_tx.shared.b64 _, [%0], %1;"
                         :: "r"(mb), "r"(CODES_BYTES + SC_BYTES) : "memory");
            asm volatile(
                "cp.async.bulk.shared::cta.global.mbarrier::complete_tx::bytes [%0], [%1], %2, [%3];"
                :: "r"(cdst), "l"(codes + (size_t)tl * TILE_GROUPS),
                   "r"((int)CODES_BYTES), "r"(mb) : "memory");
            asm volatile(
                "cp.async.bulk.shared::cta.global.mbarrier::complete_tx::bytes [%0], [%1], %2, [%3];"
                :: "r"(sdst), "l"(scales + (size_t)tl * SC_TILE),
                   "r"((int)SC_BYTES), "r"(mb) : "memory");
        }
    }
    __syncthreads();

    for (unsigned int it = 0;; ++it) {
        unsigned int tile = blockIdx.x + it * GRID;
        if (tile >= NTILES) break;

        int p  = (int)(it % NIN);
        int ph = (int)((it / NIN) & 1u);     // it ≡ p (mod 3) -> phase = (it/3)&1

        // Wait for this tile's codes+scales (acquire).
        mbar_wait(smem_u32(&mbar[p]), ph);

        unsigned int gbase = tile * TILE_GROUPS;
        const float4* cb = scb + ((gbase >= HALF_GROUPS) ? 256 : 0);

        int   c0 = cbuf[p][t];
        int   c1 = cbuf[p][TPB + t];
        float s0 = sbuf[p][t >> 4];
        float s1 = sbuf[p][(TPB + t) >> 4];
        float4 v0 = cb[c0];
        float4 v1 = cb[c1];
        v0.x *= s0; v0.y *= s0; v0.z *= s0; v0.w *= s0;
        v1.x *= s1; v1.y *= s1; v1.z *= s1; v1.w *= s1;

        // Reclaim output buffer (TMA store from 2 tiles ago done reading smem).
        if (it >= NOUT && t == 0)
            asm volatile("cp.async.bulk.wait_group.read 1;" ::: "memory");
        __syncthreads();   // also guarantees everyone is done with cbuf[(it-1)%3]

        // Prefetch iteration it+2 into buffer (it+2)%3 == (it-1)%3 (just freed).
        if (t == 0) {
            unsigned int ntile = blockIdx.x + (it + 2) * GRID;
            if (ntile < NTILES) {
                int np = (int)((it + 2) % NIN);
                uint32_t mb   = smem_u32(&mbar[np]);
                uint32_t cdst = smem_u32(&cbuf[np][0]);
                uint32_t sdst = smem_u32(&sbuf[np][0]);
                asm volatile("mbarrier.arrive.expect_tx.shared.b64 _, [%0], %1;"
                             :: "r"(mb), "r"(CODES_BYTES + SC_BYTES) : "memory");
                asm volatile(
                    "cp.async.bulk.shared::cta.global.mbarrier::complete_tx::bytes [%0], [%1], %2, [%3];"
                    :: "r"(cdst), "l"(codes + (size_t)ntile * TILE_GROUPS),
                       "r"((int)CODES_BYTES), "r"(mb) : "memory");
                asm volatile(
                    "cp.async.bulk.shared::cta.global.mbarrier::complete_tx::bytes [%0], [%1], %2, [%3];"
                    :: "r"(sdst), "l"(scales + (size_t)ntile * SC_TILE),
                       "r"((int)SC_BYTES), "r"(mb) : "memory");
            }
        }

        // Stage output tile (conflict-free STS.128) and hand to TMA.
        int b = (int)(it & 1u);
        obuf[b][t]       = v0;
        obuf[b][TPB + t] = v1;
        __syncthreads();

        if (t == 0) {
            asm volatile("fence.proxy.async.shared::cta;" ::: "memory");
            uint32_t saddr = smem_u32(&obuf[b][0]);
            const float4* gdst = out + gbase;
            asm volatile(
                "cp.async.bulk.global.shared::cta.bulk_group [%0], [%1], %2;"
                :: "l"(gdst), "r"(saddr), "r"((int)(TILE_GROUPS * 16)) : "memory");
            asm volatile("cp.async.bulk.commit_group;" ::: "memory");
        }
    }

    // Drain outstanding bulk stores before exit.
    if (t == 0)
        asm volatile("cp.async.bulk.wait_group 0;" ::: "memory");
}

extern "C" void kernel_launch(void* const* d_in, const int* in_sizes, int n_in,
                              void* d_out, int out_size)
{
    const float4* codebooks = (const float4*)d_in[0];  // [2,256,4] fp32
    const float*  scales    = (const float*) d_in[1];  // [numel/64, 1] fp32
    const int*    codes     = (const int*)   d_in[2];  // [2, numel/8] int32 flat
    float4*       out       = (float4*)d_out;          // [8192, 8192] fp32

    dequant_kernel<<<GRID, TPB>>>(codebooks, scales, codes, out);
}